// round 2
// baseline (speedup 1.0000x reference)
#include <cuda_runtime.h>

#define NB 8
#define NC 256
#define NP 4096

// Scratch (device globals — no allocation allowed in kernel_launch)
__device__ float g_q[NB * NC * NP];   // [b][c][n]
__device__ float g_k[NB * NC * NP];   // [b][c][n]
__device__ float g_v[NB * NP * NC];   // [b][n][c]  (transposed for PV stage)
__device__ float g_o[NB * NC * NP];   // [b][c][n]

typedef unsigned long long ull;

__device__ __forceinline__ ull pack2(float lo, float hi) {
    ull r; asm("mov.b64 %0, {%1, %2};" : "=l"(r) : "f"(lo), "f"(hi)); return r;
}
__device__ __forceinline__ float2 unpack2(ull v) {
    float2 r; asm("mov.b64 {%0, %1}, %2;" : "=f"(r.x), "=f"(r.y) : "l"(v)); return r;
}
__device__ __forceinline__ ull fma2(ull a, ull b, ull c) {
    ull d; asm("fma.rn.f32x2 %0, %1, %2, %3;" : "=l"(d) : "l"(a), "l"(b), "l"(c)); return d;
}
__device__ __forceinline__ ull mul2(ull a, ull b) {
    ull d; asm("mul.rn.f32x2 %0, %1, %2;" : "=l"(d) : "l"(a), "l"(b)); return d;
}

// ============================================================================
// Kernel A: fused QKV projection.
// Stacked GEMM [Wq;Wk;Wv](768x256) @ x(256x4096) per batch, then mask epilogue:
//   q = mask*(Wq@x)+bq ; k = (1-mask)*(Wk@x)+bk ; v = (1-mask)*(Wv@x)+bv
// (mask is per-position scalar, so it commutes with the 1x1 conv)
// grid (64 n-tiles, 6 m-tiles of 128, 8 b), block 256 (16x16), thread 8Mx4N.
// ============================================================================
__global__ __launch_bounds__(256, 1) void qkv_kernel(
    const float* __restrict__ x, const float* __restrict__ mask,
    const float* __restrict__ Wq, const float* __restrict__ bq,
    const float* __restrict__ Wk, const float* __restrict__ bk,
    const float* __restrict__ Wv, const float* __restrict__ bv)
{
    __shared__ float Ws[32][132];   // [k][m], padded row
    __shared__ float Xs[32][64];    // [k][n]

    const int tid = threadIdx.x;
    const int tx = tid & 15;
    const int ty = tid >> 4;
    const int n0 = blockIdx.x * 64;
    const int m0 = blockIdx.y * 128;
    const int b  = blockIdx.z;

    ull acc[4][4];   // [m-pair][jj]
    #pragma unroll
    for (int mp = 0; mp < 4; mp++)
        #pragma unroll
        for (int jj = 0; jj < 4; jj++) acc[mp][jj] = 0ull;

    for (int kc = 0; kc < NC; kc += 32) {
        #pragma unroll
        for (int it = 0; it < 16; it++) {
            int idx = tid + it * 256;
            int m = idx >> 5, kk = idx & 31;
            int mg = m0 + m;
            const float* Wp = (mg < 256) ? Wq : ((mg < 512) ? Wk : Wv);
            Ws[kk][m] = Wp[(mg & 255) * 256 + kc + kk];
        }
        #pragma unroll
        for (int it = 0; it < 2; it++) {
            int idx = tid + it * 256;
            int k = idx >> 4, j4 = idx & 15;
            *reinterpret_cast<float4*>(&Xs[k][j4 * 4]) =
                *reinterpret_cast<const float4*>(&x[(size_t)(b * NC + kc + k) * NP + n0 + j4 * 4]);
        }
        __syncthreads();
        #pragma unroll 8
        for (int k = 0; k < 32; k++) {
            ulonglong2 w01 = *reinterpret_cast<const ulonglong2*>(&Ws[k][ty * 8]);
            ulonglong2 w23 = *reinterpret_cast<const ulonglong2*>(&Ws[k][ty * 8 + 4]);
            float4 xv = *reinterpret_cast<const float4*>(&Xs[k][tx * 4]);
            ull wp[4] = { w01.x, w01.y, w23.x, w23.y };
            ull xd[4] = { pack2(xv.x, xv.x), pack2(xv.y, xv.y),
                          pack2(xv.z, xv.z), pack2(xv.w, xv.w) };
            #pragma unroll
            for (int mp = 0; mp < 4; mp++)
                #pragma unroll
                for (int jj = 0; jj < 4; jj++)
                    acc[mp][jj] = fma2(wp[mp], xd[jj], acc[mp][jj]);
        }
        __syncthreads();
    }

    const int sel = m0 >> 8;   // 0:q  1:k  2:v
    float mk[4];
    #pragma unroll
    for (int jj = 0; jj < 4; jj++) mk[jj] = mask[(size_t)b * NP + n0 + tx * 4 + jj];

    #pragma unroll
    for (int mp = 0; mp < 4; mp++) {
        float2 u[4];
        #pragma unroll
        for (int jj = 0; jj < 4; jj++) u[jj] = unpack2(acc[mp][jj]);
        #pragma unroll
        for (int h = 0; h < 2; h++) {
            int o = (m0 & 255) + ty * 8 + mp * 2 + h;
            float v0 = h ? u[0].y : u[0].x;
            float v1 = h ? u[1].y : u[1].x;
            float v2 = h ? u[2].y : u[2].x;
            float v3 = h ? u[3].y : u[3].x;
            if (sel == 0) {
                float bb = bq[o];
                float4 r = make_float4(mk[0] * v0 + bb, mk[1] * v1 + bb,
                                       mk[2] * v2 + bb, mk[3] * v3 + bb);
                *reinterpret_cast<float4*>(&g_q[(size_t)(b * NC + o) * NP + n0 + tx * 4]) = r;
            } else if (sel == 1) {
                float bb = bk[o];
                float4 r = make_float4((1.f - mk[0]) * v0 + bb, (1.f - mk[1]) * v1 + bb,
                                       (1.f - mk[2]) * v2 + bb, (1.f - mk[3]) * v3 + bb);
                *reinterpret_cast<float4*>(&g_k[(size_t)(b * NC + o) * NP + n0 + tx * 4]) = r;
            } else {
                float bb = bv[o];
                // v stored [n][c]; per (n) the 8 o's of this thread are contiguous
                g_v[(size_t)(b * NP + n0 + tx * 4 + 0) * NC + o] = (1.f - mk[0]) * v0 + bb;
                g_v[(size_t)(b * NP + n0 + tx * 4 + 1) * NC + o] = (1.f - mk[1]) * v1 + bb;
                g_v[(size_t)(b * NP + n0 + tx * 4 + 2) * NC + o] = (1.f - mk[2]) * v2 + bb;
                g_v[(size_t)(b * NP + n0 + tx * 4 + 3) * NC + o] = (1.f - mk[3]) * v3 + bb;
            }
        }
    }
}

// ============================================================================
// Kernel B: flash attention, fp32, online softmax.
// grid (64 query-tiles, 8 b), block 256.
// smem: Q[256][64] resident; stream K[256][64], Vt[64][256]; P[64][64].
// Thread map: S stage (ty,tx)->rows ty*4..+3, cols tx*4..+3 (acc packed f32x2
// along rows); PV stage thread owns c in {cc*64+tx*4+d} x i in {ty*4+ii}.
// ============================================================================
__global__ __launch_bounds__(256, 1) void attn_kernel()
{
    extern __shared__ float smf[];
    float* Qs  = smf;             // 16384
    float* Ks  = smf + 16384;     // 16384
    float* Vst = smf + 32768;     // 16384 : [j][c]
    float* Ps  = smf + 49152;     // 4096  : [i][j]

    const int tid = threadIdx.x;
    const int tx = tid & 15;
    const int ty = tid >> 4;
    const int b  = blockIdx.y;
    const int i0 = blockIdx.x * 64;

    #pragma unroll
    for (int it = 0; it < 16; it++) {
        int idx = tid + it * 256;
        int c = idx >> 4, i4 = idx & 15;
        *reinterpret_cast<float4*>(&Qs[c * 64 + i4 * 4]) =
            *reinterpret_cast<const float4*>(&g_q[(size_t)(b * NC + c) * NP + i0 + i4 * 4]);
    }

    float m_i[4], l_i[4];
    #pragma unroll
    for (int ii = 0; ii < 4; ii++) { m_i[ii] = -1e30f; l_i[ii] = 0.f; }
    ulonglong2 oa[4][4];
    #pragma unroll
    for (int cc = 0; cc < 4; cc++)
        #pragma unroll
        for (int ii = 0; ii < 4; ii++) { oa[cc][ii].x = 0ull; oa[cc][ii].y = 0ull; }

    __syncthreads();

    for (int jt = 0; jt < 64; jt++) {
        const int j0 = jt * 64;
        #pragma unroll
        for (int it = 0; it < 16; it++) {
            int idx = tid + it * 256;
            int c = idx >> 4, j4 = idx & 15;
            *reinterpret_cast<float4*>(&Ks[c * 64 + j4 * 4]) =
                *reinterpret_cast<const float4*>(&g_k[(size_t)(b * NC + c) * NP + j0 + j4 * 4]);
        }
        #pragma unroll
        for (int it = 0; it < 16; it++) {
            int idx = tid + it * 256;
            int j = idx >> 6, c4 = idx & 63;
            *reinterpret_cast<float4*>(&Vst[j * 256 + c4 * 4]) =
                *reinterpret_cast<const float4*>(&g_v[(size_t)(b * NP + j0 + j) * NC + c4 * 4]);
        }
        __syncthreads();

        // ---- S = Q^T K (64x64 tile), f32x2-packed along query rows ----
        ull s2[2][4];
        #pragma unroll
        for (int ip = 0; ip < 2; ip++)
            #pragma unroll
            for (int jj = 0; jj < 4; jj++) s2[ip][jj] = 0ull;

        #pragma unroll 4
        for (int c = 0; c < NC; c++) {
            ulonglong2 q2 = *reinterpret_cast<const ulonglong2*>(&Qs[c * 64 + ty * 4]);
            float4 k4 = *reinterpret_cast<const float4*>(&Ks[c * 64 + tx * 4]);
            ull kd[4] = { pack2(k4.x, k4.x), pack2(k4.y, k4.y),
                          pack2(k4.z, k4.z), pack2(k4.w, k4.w) };
            #pragma unroll
            for (int jj = 0; jj < 4; jj++) {
                s2[0][jj] = fma2(q2.x, kd[jj], s2[0][jj]);
                s2[1][jj] = fma2(q2.y, kd[jj], s2[1][jj]);
            }
        }

        float sv[4][4];
        #pragma unroll
        for (int ip = 0; ip < 2; ip++)
            #pragma unroll
            for (int jj = 0; jj < 4; jj++) {
                float2 u = unpack2(s2[ip][jj]);
                sv[ip * 2 + 0][jj] = u.x;
                sv[ip * 2 + 1][jj] = u.y;
            }

        // ---- online softmax (rows ty*4+ii, reduce across 16 tx lanes) ----
        float al[4];
        #pragma unroll
        for (int ii = 0; ii < 4; ii++) {
            float rm = fmaxf(fmaxf(sv[ii][0], sv[ii][1]), fmaxf(sv[ii][2], sv[ii][3]));
            #pragma unroll
            for (int off = 8; off > 0; off >>= 1)
                rm = fmaxf(rm, __shfl_xor_sync(0xffffffffu, rm, off));
            float mn = fmaxf(m_i[ii], rm);
            al[ii] = __expf(m_i[ii] - mn);
            float rs = 0.f;
            #pragma unroll
            for (int jj = 0; jj < 4; jj++) {
                float p = __expf(sv[ii][jj] - mn);
                sv[ii][jj] = p;
                rs += p;
            }
            #pragma unroll
            for (int off = 8; off > 0; off >>= 1)
                rs += __shfl_xor_sync(0xffffffffu, rs, off);
            l_i[ii] = l_i[ii] * al[ii] + rs;
            m_i[ii] = mn;
            *reinterpret_cast<float4*>(&Ps[(ty * 4 + ii) * 64 + tx * 4]) =
                make_float4(sv[ii][0], sv[ii][1], sv[ii][2], sv[ii][3]);
            ull ad = pack2(al[ii], al[ii]);
            #pragma unroll
            for (int cc = 0; cc < 4; cc++) {
                oa[cc][ii].x = mul2(oa[cc][ii].x, ad);
                oa[cc][ii].y = mul2(oa[cc][ii].y, ad);
            }
        }
        __syncthreads();

        // ---- O += V @ P^T, f32x2-packed along c ----
        for (int j4 = 0; j4 < 16; j4++) {
            float4 pr[4];
            #pragma unroll
            for (int ii = 0; ii < 4; ii++)
                pr[ii] = *reinterpret_cast<const float4*>(&Ps[(ty * 4 + ii) * 64 + j4 * 4]);
            #pragma unroll
            for (int dj = 0; dj < 4; dj++) {
                int j = j4 * 4 + dj;
                ulonglong2 vv[4];
                #pragma unroll
                for (int cc = 0; cc < 4; cc++)
                    vv[cc] = *reinterpret_cast<const ulonglong2*>(&Vst[j * 256 + cc * 64 + tx * 4]);
                #pragma unroll
                for (int ii = 0; ii < 4; ii++) {
                    float p = (dj == 0) ? pr[ii].x : (dj == 1) ? pr[ii].y
                            : (dj == 2) ? pr[ii].z : pr[ii].w;
                    ull pd = pack2(p, p);
                    #pragma unroll
                    for (int cc = 0; cc < 4; cc++) {
                        oa[cc][ii].x = fma2(vv[cc].x, pd, oa[cc][ii].x);
                        oa[cc][ii].y = fma2(vv[cc].y, pd, oa[cc][ii].y);
                    }
                }
            }
        }
        __syncthreads();
    }

    float inv[4];
    #pragma unroll
    for (int ii = 0; ii < 4; ii++) inv[ii] = 1.f / l_i[ii];

    #pragma unroll
    for (int cc = 0; cc < 4; cc++) {
        float of[4][4];
        #pragma unroll
        for (int ii = 0; ii < 4; ii++) {
            float2 u0 = unpack2(oa[cc][ii].x);
            float2 u1 = unpack2(oa[cc][ii].y);
            of[ii][0] = u0.x * inv[ii];
            of[ii][1] = u0.y * inv[ii];
            of[ii][2] = u1.x * inv[ii];
            of[ii][3] = u1.y * inv[ii];
        }
        #pragma unroll
        for (int d = 0; d < 4; d++) {
            int c = cc * 64 + tx * 4 + d;
            *reinterpret_cast<float4*>(&g_o[(size_t)(b * NC + c) * NP + i0 + ty * 4]) =
                make_float4(of[0][d], of[1][d], of[2][d], of[3][d]);
        }
    }
}

// ============================================================================
// Kernel C: output projection + residual: out = Wo@O + bo + gamma*x
// grid (64 n-tiles, 2 m-tiles, 8 b)
// ============================================================================
__global__ __launch_bounds__(256, 1) void proj_kernel(
    const float* __restrict__ xin, const float* __restrict__ Wo,
    const float* __restrict__ bo, const float* __restrict__ gamma,
    float* __restrict__ out)
{
    __shared__ float Ws[32][132];
    __shared__ float Xs[32][64];

    const int tid = threadIdx.x;
    const int tx = tid & 15;
    const int ty = tid >> 4;
    const int n0 = blockIdx.x * 64;
    const int m0 = blockIdx.y * 128;
    const int b  = blockIdx.z;

    ull acc[4][4];
    #pragma unroll
    for (int mp = 0; mp < 4; mp++)
        #pragma unroll
        for (int jj = 0; jj < 4; jj++) acc[mp][jj] = 0ull;

    for (int kc = 0; kc < NC; kc += 32) {
        #pragma unroll
        for (int it = 0; it < 16; it++) {
            int idx = tid + it * 256;
            int m = idx >> 5, kk = idx & 31;
            Ws[kk][m] = Wo[(m0 + m) * 256 + kc + kk];
        }
        #pragma unroll
        for (int it = 0; it < 2; it++) {
            int idx = tid + it * 256;
            int k = idx >> 4, j4 = idx & 15;
            *reinterpret_cast<float4*>(&Xs[k][j4 * 4]) =
                *reinterpret_cast<const float4*>(&g_o[(size_t)(b * NC + kc + k) * NP + n0 + j4 * 4]);
        }
        __syncthreads();
        #pragma unroll 8
        for (int k = 0; k < 32; k++) {
            ulonglong2 w01 = *reinterpret_cast<const ulonglong2*>(&Ws[k][ty * 8]);
            ulonglong2 w23 = *reinterpret_cast<const ulonglong2*>(&Ws[k][ty * 8 + 4]);
            float4 xv = *reinterpret_cast<const float4*>(&Xs[k][tx * 4]);
            ull wp[4] = { w01.x, w01.y, w23.x, w23.y };
            ull xd[4] = { pack2(xv.x, xv.x), pack2(xv.y, xv.y),
                          pack2(xv.z, xv.z), pack2(xv.w, xv.w) };
            #pragma unroll
            for (int mp = 0; mp < 4; mp++)
                #pragma unroll
                for (int jj = 0; jj < 4; jj++)
                    acc[mp][jj] = fma2(wp[mp], xd[jj], acc[mp][jj]);
        }
        __syncthreads();
    }

    const float g0 = gamma[0];
    #pragma unroll
    for (int mp = 0; mp < 4; mp++) {
        float2 u[4];
        #pragma unroll
        for (int jj = 0; jj < 4; jj++) u[jj] = unpack2(acc[mp][jj]);
        #pragma unroll
        for (int h = 0; h < 2; h++) {
            int o = m0 + ty * 8 + mp * 2 + h;
            float bb = bo[o];
            float4 xr = *reinterpret_cast<const float4*>(&xin[(size_t)(b * NC + o) * NP + n0 + tx * 4]);
            float4 r;
            r.x = (h ? u[0].y : u[0].x) + bb + g0 * xr.x;
            r.y = (h ? u[1].y : u[1].x) + bb + g0 * xr.y;
            r.z = (h ? u[2].y : u[2].x) + bb + g0 * xr.z;
            r.w = (h ? u[3].y : u[3].x) + bb + g0 * xr.w;
            *reinterpret_cast<float4*>(&out[(size_t)(b * NC + o) * NP + n0 + tx * 4]) = r;
        }
    }
}

extern "C" void kernel_launch(void* const* d_in, const int* in_sizes, int n_in,
                              void* d_out, int out_size)
{
    const float* x     = (const float*)d_in[0];
    const float* mask  = (const float*)d_in[1];
    const float* Wq    = (const float*)d_in[2];
    const float* bq    = (const float*)d_in[3];
    const float* Wk    = (const float*)d_in[4];
    const float* bk    = (const float*)d_in[5];
    const float* Wv    = (const float*)d_in[6];
    const float* bv    = (const float*)d_in[7];
    const float* Wo    = (const float*)d_in[8];
    const float* bo    = (const float*)d_in[9];
    const float* gamma = (const float*)d_in[10];
    float* out = (float*)d_out;

    qkv_kernel<<<dim3(64, 6, NB), 256>>>(x, mask, Wq, bq, Wk, bk, Wv, bv);

    const size_t smemB = (size_t)(16384 * 3 + 4096) * sizeof(float);  // 212992 B
    cudaFuncSetAttribute(attn_kernel, cudaFuncAttributeMaxDynamicSharedMemorySize, (int)smemB);
    attn_kernel<<<dim3(64, NB), 256, smemB>>>();

    proj_kernel<<<dim3(64, 2, NB), 256>>>(x, Wo, bo, gamma, out);
}

// round 3
// speedup vs baseline: 2.8402x; 2.8402x over previous
#include <cuda_runtime.h>

#define NB 8
#define NC 256
#define NP 4096
#define NPQ 4160   // max padded compacted columns: round_up(4096+1, 64)

// Scratch (device globals — no allocation allowed)
__device__ float g_q[NB * NC * NP];    // dense q [b][c][n]
__device__ float g_k[NB * NC * NP];    // dense k [b][c][n]
__device__ float g_v[NB * NP * NC];    // dense v [b][n][c]
__device__ float g_pq[NB * NC * NPQ];  // packed q [b][c][p]  (fg cols + bq + 0-pad)
__device__ float g_pk[NB * NC * NPQ];  // packed k [b][c][p]  (bg cols + bk + 0-pad)
__device__ float g_pv[NB * NPQ * NC];  // packed v [b][p][c]
__device__ float g_go[NB * NC * NPQ];  // attention out (packed cols)
__device__ float g_p [NB * NC * NPQ];  // proj out (packed cols)
__device__ int   g_fidx[NB * NP];
__device__ int   g_bidx[NB * NP];
__device__ int   g_cidx[NB * NP];
__device__ int   g_cnt[NB * 2];        // nf, nb per batch

typedef unsigned long long ull;

__device__ __forceinline__ ull pack2(float lo, float hi) {
    ull r; asm("mov.b64 %0, {%1, %2};" : "=l"(r) : "f"(lo), "f"(hi)); return r;
}
__device__ __forceinline__ float2 unpack2(ull v) {
    float2 r; asm("mov.b64 {%0, %1}, %2;" : "=f"(r.x), "=f"(r.y) : "l"(v)); return r;
}
__device__ __forceinline__ ull fma2(ull a, ull b, ull c) {
    ull d; asm("fma.rn.f32x2 %0, %1, %2, %3;" : "=l"(d) : "l"(a), "l"(b), "l"(c)); return d;
}
__device__ __forceinline__ ull mul2(ull a, ull b) {
    ull d; asm("mul.rn.f32x2 %0, %1, %2;" : "=l"(d) : "l"(a), "l"(b)); return d;
}

// ============================================================================
// Compaction: deterministic prefix scan of the 0/1 mask per batch.
// fidx: positions with mask=1 (queries), bidx: mask=0 (keys/values),
// cidx[n]: packed output column for position n (fpos, or nf for shared col).
// ============================================================================
__global__ __launch_bounds__(256, 1) void compact_kernel(const float* __restrict__ mask)
{
    const int b = blockIdx.x;
    const int tid = threadIdx.x;
    const int lane = tid & 31, wid = tid >> 5;
    __shared__ int wsum[8];
    __shared__ int s_nf;

    bool f[16];
    int c = 0;
    const float* mb = mask + (size_t)b * NP;
    #pragma unroll
    for (int i = 0; i < 16; i++) { f[i] = mb[tid * 16 + i] > 0.5f; c += f[i]; }

    int v = c;
    #pragma unroll
    for (int off = 1; off < 32; off <<= 1) {
        int u = __shfl_up_sync(0xffffffffu, v, off);
        if (lane >= off) v += u;
    }
    if (lane == 31) wsum[wid] = v;
    __syncthreads();
    if (tid < 8) {
        int wv = wsum[tid];
        #pragma unroll
        for (int off = 1; off < 8; off <<= 1) {
            int u = __shfl_up_sync(0xffu, wv, off);
            if (tid >= off) wv += u;
        }
        wsum[tid] = wv;                 // inclusive warp totals
        if (tid == 7) s_nf = wv;
    }
    __syncthreads();
    const int nf = s_nf;
    int excl = v - c + (wid ? wsum[wid - 1] : 0);
    int fo = excl;
    int bo = tid * 16 - excl;

    int* fidx = g_fidx + (size_t)b * NP;
    int* bidx = g_bidx + (size_t)b * NP;
    int* cidx = g_cidx + (size_t)b * NP;
    #pragma unroll
    for (int i = 0; i < 16; i++) {
        int n = tid * 16 + i;
        if (f[i]) { fidx[fo] = n; cidx[n] = fo; fo++; }
        else      { bidx[bo] = n; cidx[n] = nf; bo++; }
    }
    if (tid == 0) { g_cnt[b * 2] = nf; g_cnt[b * 2 + 1] = NP - nf; }
}

// ============================================================================
// Kernel A: fused dense QKV projection (unchanged from R1).
// ============================================================================
__global__ __launch_bounds__(256, 1) void qkv_kernel(
    const float* __restrict__ x, const float* __restrict__ mask,
    const float* __restrict__ Wq, const float* __restrict__ bq,
    const float* __restrict__ Wk, const float* __restrict__ bk,
    const float* __restrict__ Wv, const float* __restrict__ bv)
{
    __shared__ float Ws[32][132];
    __shared__ float Xs[32][64];

    const int tid = threadIdx.x;
    const int tx = tid & 15;
    const int ty = tid >> 4;
    const int n0 = blockIdx.x * 64;
    const int m0 = blockIdx.y * 128;
    const int b  = blockIdx.z;

    ull acc[4][4];
    #pragma unroll
    for (int mp = 0; mp < 4; mp++)
        #pragma unroll
        for (int jj = 0; jj < 4; jj++) acc[mp][jj] = 0ull;

    for (int kc = 0; kc < NC; kc += 32) {
        #pragma unroll
        for (int it = 0; it < 16; it++) {
            int idx = tid + it * 256;
            int m = idx >> 5, kk = idx & 31;
            int mg = m0 + m;
            const float* Wp = (mg < 256) ? Wq : ((mg < 512) ? Wk : Wv);
            Ws[kk][m] = Wp[(mg & 255) * 256 + kc + kk];
        }
        #pragma unroll
        for (int it = 0; it < 2; it++) {
            int idx = tid + it * 256;
            int k = idx >> 4, j4 = idx & 15;
            *reinterpret_cast<float4*>(&Xs[k][j4 * 4]) =
                *reinterpret_cast<const float4*>(&x[(size_t)(b * NC + kc + k) * NP + n0 + j4 * 4]);
        }
        __syncthreads();
        #pragma unroll 8
        for (int k = 0; k < 32; k++) {
            ulonglong2 w01 = *reinterpret_cast<const ulonglong2*>(&Ws[k][ty * 8]);
            ulonglong2 w23 = *reinterpret_cast<const ulonglong2*>(&Ws[k][ty * 8 + 4]);
            float4 xv = *reinterpret_cast<const float4*>(&Xs[k][tx * 4]);
            ull wp[4] = { w01.x, w01.y, w23.x, w23.y };
            ull xd[4] = { pack2(xv.x, xv.x), pack2(xv.y, xv.y),
                          pack2(xv.z, xv.z), pack2(xv.w, xv.w) };
            #pragma unroll
            for (int mp = 0; mp < 4; mp++)
                #pragma unroll
                for (int jj = 0; jj < 4; jj++)
                    acc[mp][jj] = fma2(wp[mp], xd[jj], acc[mp][jj]);
        }
        __syncthreads();
    }

    const int sel = m0 >> 8;
    float mk[4];
    #pragma unroll
    for (int jj = 0; jj < 4; jj++) mk[jj] = mask[(size_t)b * NP + n0 + tx * 4 + jj];

    #pragma unroll
    for (int mp = 0; mp < 4; mp++) {
        float2 u[4];
        #pragma unroll
        for (int jj = 0; jj < 4; jj++) u[jj] = unpack2(acc[mp][jj]);
        #pragma unroll
        for (int h = 0; h < 2; h++) {
            int o = (m0 & 255) + ty * 8 + mp * 2 + h;
            float v0 = h ? u[0].y : u[0].x;
            float v1 = h ? u[1].y : u[1].x;
            float v2 = h ? u[2].y : u[2].x;
            float v3 = h ? u[3].y : u[3].x;
            if (sel == 0) {
                float bb = bq[o];
                float4 r = make_float4(mk[0] * v0 + bb, mk[1] * v1 + bb,
                                       mk[2] * v2 + bb, mk[3] * v3 + bb);
                *reinterpret_cast<float4*>(&g_q[(size_t)(b * NC + o) * NP + n0 + tx * 4]) = r;
            } else if (sel == 1) {
                float bb = bk[o];
                float4 r = make_float4((1.f - mk[0]) * v0 + bb, (1.f - mk[1]) * v1 + bb,
                                       (1.f - mk[2]) * v2 + bb, (1.f - mk[3]) * v3 + bb);
                *reinterpret_cast<float4*>(&g_k[(size_t)(b * NC + o) * NP + n0 + tx * 4]) = r;
            } else {
                float bb = bv[o];
                g_v[(size_t)(b * NP + n0 + tx * 4 + 0) * NC + o] = (1.f - mk[0]) * v0 + bb;
                g_v[(size_t)(b * NP + n0 + tx * 4 + 1) * NC + o] = (1.f - mk[1]) * v1 + bb;
                g_v[(size_t)(b * NP + n0 + tx * 4 + 2) * NC + o] = (1.f - mk[2]) * v2 + bb;
                g_v[(size_t)(b * NP + n0 + tx * 4 + 3) * NC + o] = (1.f - mk[3]) * v3 + bb;
            }
        }
    }
}

// ============================================================================
// Pack: gather dense q/k/v into compacted buffers, append bq/bk/bv column,
// zero-pad to 64-multiple. grid (64, 3, 8), block 256.
// ============================================================================
__global__ __launch_bounds__(256, 1) void pack_kernel(
    const float* __restrict__ bq, const float* __restrict__ bk,
    const float* __restrict__ bv)
{
    const int b = blockIdx.z;
    const int sec = blockIdx.y;
    const int tid = threadIdx.x;
    const int nf = g_cnt[b * 2];
    const int nb = g_cnt[b * 2 + 1];

    if (sec == 0) {
        const int NQ = ((nf + 64) >> 6) << 6;
        const int* fidx = g_fidx + (size_t)b * NP;
        int c0 = blockIdx.x * 4;
        for (int c = c0; c < c0 + 4; c++) {
            const float* src = g_q + (size_t)(b * NC + c) * NP;
            float* dst = g_pq + (size_t)(b * NC + c) * NPQ;
            float bias = bq[c];
            for (int p = tid; p < NQ; p += 256)
                dst[p] = (p < nf) ? src[fidx[p]] : ((p == nf) ? bias : 0.f);
        }
    } else if (sec == 1) {
        const int NK = ((nb + 64) >> 6) << 6;
        const int* bidx = g_bidx + (size_t)b * NP;
        int c0 = blockIdx.x * 4;
        for (int c = c0; c < c0 + 4; c++) {
            const float* src = g_k + (size_t)(b * NC + c) * NP;
            float* dst = g_pk + (size_t)(b * NC + c) * NPQ;
            float bias = bk[c];
            for (int p = tid; p < NK; p += 256)
                dst[p] = (p < nb) ? src[bidx[p]] : ((p == nb) ? bias : 0.f);
        }
    } else {
        const int NK = ((nb + 64) >> 6) << 6;
        const int* bidx = g_bidx + (size_t)b * NP;
        for (int p = blockIdx.x; p < NK; p += 64) {
            float val;
            if (p < nb)       val = g_v[((size_t)b * NP + bidx[p]) * NC + tid];
            else if (p == nb) val = bv[tid];
            else              val = 0.f;
            g_pv[((size_t)b * NPQ + p) * NC + tid] = val;
        }
    }
}

// ============================================================================
// Kernel B: flash attention on compacted columns with weighted shared key.
// Queries: nf real + 1 shared (bq). Keys: nb real + bk with weight nf.
// grid (65 query-tiles, 8 b), block 256; early exit on runtime count.
// ============================================================================
__global__ __launch_bounds__(256, 1) void attn_kernel()
{
    extern __shared__ float smf[];
    float* Qs  = smf;             // 16384
    float* Ks  = smf + 16384;     // 16384
    float* Vst = smf + 32768;     // 16384 : [j][c]
    float* Ps  = smf + 49152;     // 4096  : [i][j]

    const int tid = threadIdx.x;
    const int tx = tid & 15;
    const int ty = tid >> 4;
    const int b  = blockIdx.y;
    const int i0 = blockIdx.x * 64;

    const int nf = g_cnt[b * 2];
    const int nb = g_cnt[b * 2 + 1];
    if (i0 >= nf + 1) return;           // inactive query tile
    const int nkt = (nb + 1 + 63) >> 6; // key tiles (incl. shared bk key)
    const float wF = (float)nf;         // multiplicity of shared key

    #pragma unroll
    for (int it = 0; it < 16; it++) {
        int idx = tid + it * 256;
        int c = idx >> 4, i4 = idx & 15;
        *reinterpret_cast<float4*>(&Qs[c * 64 + i4 * 4]) =
            *reinterpret_cast<const float4*>(&g_pq[(size_t)(b * NC + c) * NPQ + i0 + i4 * 4]);
    }

    float m_i[4], l_i[4];
    #pragma unroll
    for (int ii = 0; ii < 4; ii++) { m_i[ii] = -1e30f; l_i[ii] = 0.f; }
    ulonglong2 oa[4][4];
    #pragma unroll
    for (int cc = 0; cc < 4; cc++)
        #pragma unroll
        for (int ii = 0; ii < 4; ii++) { oa[cc][ii].x = 0ull; oa[cc][ii].y = 0ull; }

    __syncthreads();

    for (int jt = 0; jt < nkt; jt++) {
        const int j0 = jt * 64;
        #pragma unroll
        for (int it = 0; it < 16; it++) {
            int idx = tid + it * 256;
            int c = idx >> 4, j4 = idx & 15;
            *reinterpret_cast<float4*>(&Ks[c * 64 + j4 * 4]) =
                *reinterpret_cast<const float4*>(&g_pk[(size_t)(b * NC + c) * NPQ + j0 + j4 * 4]);
        }
        #pragma unroll
        for (int it = 0; it < 16; it++) {
            int idx = tid + it * 256;
            int j = idx >> 6, c4 = idx & 63;
            *reinterpret_cast<float4*>(&Vst[j * 256 + c4 * 4]) =
                *reinterpret_cast<const float4*>(&g_pv[((size_t)b * NPQ + j0 + j) * NC + c4 * 4]);
        }
        __syncthreads();

        // ---- S = Q^T K ----
        ull s2[2][4];
        #pragma unroll
        for (int ip = 0; ip < 2; ip++)
            #pragma unroll
            for (int jj = 0; jj < 4; jj++) s2[ip][jj] = 0ull;

        #pragma unroll 4
        for (int c = 0; c < NC; c++) {
            ulonglong2 q2 = *reinterpret_cast<const ulonglong2*>(&Qs[c * 64 + ty * 4]);
            float4 k4 = *reinterpret_cast<const float4*>(&Ks[c * 64 + tx * 4]);
            ull kd[4] = { pack2(k4.x, k4.x), pack2(k4.y, k4.y),
                          pack2(k4.z, k4.z), pack2(k4.w, k4.w) };
            #pragma unroll
            for (int jj = 0; jj < 4; jj++) {
                s2[0][jj] = fma2(q2.x, kd[jj], s2[0][jj]);
                s2[1][jj] = fma2(q2.y, kd[jj], s2[1][jj]);
            }
        }

        float sv[4][4];
        #pragma unroll
        for (int ip = 0; ip < 2; ip++)
            #pragma unroll
            for (int jj = 0; jj < 4; jj++) {
                float2 u = unpack2(s2[ip][jj]);
                sv[ip * 2 + 0][jj] = u.x;
                sv[ip * 2 + 1][jj] = u.y;
            }

        // per-column weight / validity
        const int jbase = j0 + tx * 4;
        float w[4];
        #pragma unroll
        for (int jj = 0; jj < 4; jj++) {
            int jg = jbase + jj;
            w[jj] = (jg == nb) ? wF : 1.f;
            if (jg > nb) {
                #pragma unroll
                for (int ii = 0; ii < 4; ii++) sv[ii][jj] = -1e30f;
            }
        }

        // ---- online softmax ----
        float al[4];
        #pragma unroll
        for (int ii = 0; ii < 4; ii++) {
            float rm = fmaxf(fmaxf(sv[ii][0], sv[ii][1]), fmaxf(sv[ii][2], sv[ii][3]));
            #pragma unroll
            for (int off = 8; off > 0; off >>= 1)
                rm = fmaxf(rm, __shfl_xor_sync(0xffffffffu, rm, off));
            float mn = fmaxf(m_i[ii], rm);
            al[ii] = __expf(m_i[ii] - mn);
            float rs = 0.f;
            #pragma unroll
            for (int jj = 0; jj < 4; jj++) {
                float p = __expf(sv[ii][jj] - mn) * w[jj];
                sv[ii][jj] = p;
                rs += p;
            }
            #pragma unroll
            for (int off = 8; off > 0; off >>= 1)
                rs += __shfl_xor_sync(0xffffffffu, rs, off);
            l_i[ii] = l_i[ii] * al[ii] + rs;
            m_i[ii] = mn;
            *reinterpret_cast<float4*>(&Ps[(ty * 4 + ii) * 64 + tx * 4]) =
                make_float4(sv[ii][0], sv[ii][1], sv[ii][2], sv[ii][3]);
            ull ad = pack2(al[ii], al[ii]);
            #pragma unroll
            for (int cc = 0; cc < 4; cc++) {
                oa[cc][ii].x = mul2(oa[cc][ii].x, ad);
                oa[cc][ii].y = mul2(oa[cc][ii].y, ad);
            }
        }
        __syncthreads();

        // ---- O += V @ P^T ----
        for (int j4 = 0; j4 < 16; j4++) {
            float4 pr[4];
            #pragma unroll
            for (int ii = 0; ii < 4; ii++)
                pr[ii] = *reinterpret_cast<const float4*>(&Ps[(ty * 4 + ii) * 64 + j4 * 4]);
            #pragma unroll
            for (int dj = 0; dj < 4; dj++) {
                int j = j4 * 4 + dj;
                ulonglong2 vv[4];
                #pragma unroll
                for (int cc = 0; cc < 4; cc++)
                    vv[cc] = *reinterpret_cast<const ulonglong2*>(&Vst[j * 256 + cc * 64 + tx * 4]);
                #pragma unroll
                for (int ii = 0; ii < 4; ii++) {
                    float p = (dj == 0) ? pr[ii].x : (dj == 1) ? pr[ii].y
                            : (dj == 2) ? pr[ii].z : pr[ii].w;
                    ull pd = pack2(p, p);
                    #pragma unroll
                    for (int cc = 0; cc < 4; cc++) {
                        oa[cc][ii].x = fma2(vv[cc].x, pd, oa[cc][ii].x);
                        oa[cc][ii].y = fma2(vv[cc].y, pd, oa[cc][ii].y);
                    }
                }
            }
        }
        __syncthreads();
    }

    float inv[4];
    #pragma unroll
    for (int ii = 0; ii < 4; ii++) inv[ii] = 1.f / l_i[ii];

    #pragma unroll
    for (int cc = 0; cc < 4; cc++) {
        float of[4][4];
        #pragma unroll
        for (int ii = 0; ii < 4; ii++) {
            float2 u0 = unpack2(oa[cc][ii].x);
            float2 u1 = unpack2(oa[cc][ii].y);
            of[ii][0] = u0.x * inv[ii];
            of[ii][1] = u0.y * inv[ii];
            of[ii][2] = u1.x * inv[ii];
            of[ii][3] = u1.y * inv[ii];
        }
        #pragma unroll
        for (int d = 0; d < 4; d++) {
            int c = cc * 64 + tx * 4 + d;
            *reinterpret_cast<float4*>(&g_go[(size_t)(b * NC + c) * NPQ + i0 + ty * 4]) =
                make_float4(of[0][d], of[1][d], of[2][d], of[3][d]);
        }
    }
}

// ============================================================================
// Kernel C: output projection on packed columns: g_p = Wo@go + bo
// grid (65 n-tiles, 2 m-tiles, 8 b), early exit.
// ============================================================================
__global__ __launch_bounds__(256, 1) void proj_kernel(
    const float* __restrict__ Wo, const float* __restrict__ bo)
{
    __shared__ float Ws[32][132];
    __shared__ float Xs[32][64];

    const int tid = threadIdx.x;
    const int tx = tid & 15;
    const int ty = tid >> 4;
    const int n0 = blockIdx.x * 64;
    const int m0 = blockIdx.y * 128;
    const int b  = blockIdx.z;

    const int nfq = g_cnt[b * 2] + 1;
    if (n0 >= nfq) return;

    ull acc[4][4];
    #pragma unroll
    for (int mp = 0; mp < 4; mp++)
        #pragma unroll
        for (int jj = 0; jj < 4; jj++) acc[mp][jj] = 0ull;

    for (int kc = 0; kc < NC; kc += 32) {
        #pragma unroll
        for (int it = 0; it < 16; it++) {
            int idx = tid + it * 256;
            int m = idx >> 5, kk = idx & 31;
            Ws[kk][m] = Wo[(m0 + m) * 256 + kc + kk];
        }
        #pragma unroll
        for (int it = 0; it < 2; it++) {
            int idx = tid + it * 256;
            int k = idx >> 4, j4 = idx & 15;
            *reinterpret_cast<float4*>(&Xs[k][j4 * 4]) =
                *reinterpret_cast<const float4*>(&g_go[(size_t)(b * NC + kc + k) * NPQ + n0 + j4 * 4]);
        }
        __syncthreads();
        #pragma unroll 8
        for (int k = 0; k < 32; k++) {
            ulonglong2 w01 = *reinterpret_cast<const ulonglong2*>(&Ws[k][ty * 8]);
            ulonglong2 w23 = *reinterpret_cast<const ulonglong2*>(&Ws[k][ty * 8 + 4]);
            float4 xv = *reinterpret_cast<const float4*>(&Xs[k][tx * 4]);
            ull wp[4] = { w01.x, w01.y, w23.x, w23.y };
            ull xd[4] = { pack2(xv.x, xv.x), pack2(xv.y, xv.y),
                          pack2(xv.z, xv.z), pack2(xv.w, xv.w) };
            #pragma unroll
            for (int mp = 0; mp < 4; mp++)
                #pragma unroll
                for (int jj = 0; jj < 4; jj++)
                    acc[mp][jj] = fma2(wp[mp], xd[jj], acc[mp][jj]);
        }
        __syncthreads();
    }

    #pragma unroll
    for (int mp = 0; mp < 4; mp++) {
        float2 u[4];
        #pragma unroll
        for (int jj = 0; jj < 4; jj++) u[jj] = unpack2(acc[mp][jj]);
        #pragma unroll
        for (int h = 0; h < 2; h++) {
            int o = m0 + ty * 8 + mp * 2 + h;
            float bb = bo[o];
            float4 r;
            r.x = (h ? u[0].y : u[0].x) + bb;
            r.y = (h ? u[1].y : u[1].x) + bb;
            r.z = (h ? u[2].y : u[2].x) + bb;
            r.w = (h ? u[3].y : u[3].x) + bb;
            *reinterpret_cast<float4*>(&g_p[(size_t)(b * NC + o) * NPQ + n0 + tx * 4]) = r;
        }
    }
}

// ============================================================================
// Scatter: out[b][c][n] = g_p[b][c][cidx[n]] + gamma * x[b][c][n]
// grid (16, 8), block 256.
// ============================================================================
__global__ __launch_bounds__(256, 1) void scatter_kernel(
    const float* __restrict__ x, const float* __restrict__ gamma,
    float* __restrict__ out)
{
    const int b = blockIdx.y;
    const int n = blockIdx.x * 256 + threadIdx.x;
    const int ci = g_cidx[(size_t)b * NP + n];
    const float g0 = gamma[0];

    const float* px = x + (size_t)b * NC * NP + n;
    const float* pp = g_p + (size_t)b * NC * NPQ + ci;
    float* po = out + (size_t)b * NC * NP + n;

    #pragma unroll 4
    for (int c = 0; c < NC; c++) {
        po[(size_t)c * NP] = pp[(size_t)c * NPQ] + g0 * px[(size_t)c * NP];
    }
}

extern "C" void kernel_launch(void* const* d_in, const int* in_sizes, int n_in,
                              void* d_out, int out_size)
{
    const float* x     = (const float*)d_in[0];
    const float* mask  = (const float*)d_in[1];
    const float* Wq    = (const float*)d_in[2];
    const float* bq    = (const float*)d_in[3];
    const float* Wk    = (const float*)d_in[4];
    const float* bk    = (const float*)d_in[5];
    const float* Wv    = (const float*)d_in[6];
    const float* bv    = (const float*)d_in[7];
    const float* Wo    = (const float*)d_in[8];
    const float* bo    = (const float*)d_in[9];
    const float* gamma = (const float*)d_in[10];
    float* out = (float*)d_out;

    compact_kernel<<<NB, 256>>>(mask);
    qkv_kernel<<<dim3(64, 6, NB), 256>>>(x, mask, Wq, bq, Wk, bk, Wv, bv);
    pack_kernel<<<dim3(64, 3, NB), 256>>>(bq, bk, bv);

    const size_t smemB = (size_t)(16384 * 3 + 4096) * sizeof(float);  // 212992 B
    cudaFuncSetAttribute(attn_kernel, cudaFuncAttributeMaxDynamicSharedMemorySize, (int)smemB);
    attn_kernel<<<dim3(65, NB), 256, smemB>>>();

    proj_kernel<<<dim3(65, 2, NB), 256>>>(Wo, bo);
    scatter_kernel<<<dim3(16, NB), 256>>>(x, gamma, out);
}

// round 4
// speedup vs baseline: 3.2757x; 1.1533x over previous
#include <cuda_runtime.h>

#define NB 8
#define NC 256
#define NP 4096
#define NPQ 4160   // max padded compacted columns: round_up(4096+1, 64)

// Scratch (device globals — no allocation allowed)
__device__ float g_pq[NB * NC * NPQ];  // packed q [b][c][p]  (fg cols + bq + 0-pad)
__device__ float g_pk[NB * NC * NPQ];  // packed k [b][c][p]  (bg cols + bk + 0-pad)
__device__ float g_pv[NB * NPQ * NC];  // packed v [b][p][c]
__device__ float g_go[NB * NC * NPQ];  // attention out (packed cols)
__device__ float g_p [NB * NC * NPQ];  // proj out (packed cols)
__device__ int   g_pr[NB * NP];        // rank within own class (fg or bg)
__device__ int   g_cidx[NB * NP];      // packed col for scatter (fg rank, or nf)
__device__ int   g_cnt[NB * 2];        // nf, nb per batch

typedef unsigned long long ull;

__device__ __forceinline__ ull pack2(float lo, float hi) {
    ull r; asm("mov.b64 %0, {%1, %2};" : "=l"(r) : "f"(lo), "f"(hi)); return r;
}
__device__ __forceinline__ float2 unpack2(ull v) {
    float2 r; asm("mov.b64 {%0, %1}, %2;" : "=f"(r.x), "=f"(r.y) : "l"(v)); return r;
}
__device__ __forceinline__ ull fma2(ull a, ull b, ull c) {
    ull d; asm("fma.rn.f32x2 %0, %1, %2, %3;" : "=l"(d) : "l"(a), "l"(b), "l"(c)); return d;
}
__device__ __forceinline__ ull mul2(ull a, ull b) {
    ull d; asm("mul.rn.f32x2 %0, %1, %2;" : "=l"(d) : "l"(a), "l"(b)); return d;
}
__device__ __forceinline__ void cp16(void* dst, const void* src) {
    unsigned s = (unsigned)__cvta_generic_to_shared(dst);
    asm volatile("cp.async.cg.shared.global [%0], [%1], 16;" :: "r"(s), "l"(src));
}
__device__ __forceinline__ void cp4(void* dst, const void* src) {
    unsigned s = (unsigned)__cvta_generic_to_shared(dst);
    asm volatile("cp.async.ca.shared.global [%0], [%1], 4;" :: "r"(s), "l"(src));
}
#define CP_COMMIT asm volatile("cp.async.commit_group;" ::: "memory")
#define CP_WAIT(n) asm volatile("cp.async.wait_group %0;" :: "n"(n) : "memory")

// ============================================================================
// Compaction: deterministic prefix scan of the 0/1 mask per batch.
// ============================================================================
__global__ __launch_bounds__(256, 1) void compact_kernel(const float* __restrict__ mask)
{
    const int b = blockIdx.x;
    const int tid = threadIdx.x;
    const int lane = tid & 31, wid = tid >> 5;
    __shared__ int wsum[8];
    __shared__ int s_nf;

    bool f[16];
    int c = 0;
    const float* mb = mask + (size_t)b * NP;
    #pragma unroll
    for (int i = 0; i < 16; i++) { f[i] = mb[tid * 16 + i] > 0.5f; c += f[i]; }

    int v = c;
    #pragma unroll
    for (int off = 1; off < 32; off <<= 1) {
        int u = __shfl_up_sync(0xffffffffu, v, off);
        if (lane >= off) v += u;
    }
    if (lane == 31) wsum[wid] = v;
    __syncthreads();
    if (tid < 8) {
        int wv = wsum[tid];
        #pragma unroll
        for (int off = 1; off < 8; off <<= 1) {
            int u = __shfl_up_sync(0xffu, wv, off);
            if (tid >= off) wv += u;
        }
        wsum[tid] = wv;
        if (tid == 7) s_nf = wv;
    }
    __syncthreads();
    const int nf = s_nf;
    int excl = v - c + (wid ? wsum[wid - 1] : 0);
    int fo = excl;
    int bo = tid * 16 - excl;

    int* pr   = g_pr   + (size_t)b * NP;
    int* cidx = g_cidx + (size_t)b * NP;
    #pragma unroll
    for (int i = 0; i < 16; i++) {
        int n = tid * 16 + i;
        if (f[i]) { pr[n] = fo; cidx[n] = fo; fo++; }
        else      { pr[n] = bo; cidx[n] = nf; bo++; }
    }
    if (tid == 0) { g_cnt[b * 2] = nf; g_cnt[b * 2 + 1] = NP - nf; }
}

// ============================================================================
// Kernel A: fused dense QKV projection, cp.async double-buffered, epilogue
// writes DIRECTLY into compacted buffers (pack fused away).
// grid (64 n-tiles, 6 m-tiles of 128, 8 b), block 256.
// ============================================================================
__global__ __launch_bounds__(256, 1) void qkv_kernel(
    const float* __restrict__ x, const float* __restrict__ mask,
    const float* __restrict__ Wq, const float* __restrict__ bq,
    const float* __restrict__ Wk, const float* __restrict__ bk,
    const float* __restrict__ Wv, const float* __restrict__ bv)
{
    __shared__ float Ws[2][32][132];
    __shared__ float Xs[2][32][64];

    const int tid = threadIdx.x;
    const int tx = tid & 15;
    const int ty = tid >> 4;
    const int n0 = blockIdx.x * 64;
    const int m0 = blockIdx.y * 128;
    const int b  = blockIdx.z;

    ull acc[4][4];
    #pragma unroll
    for (int mp = 0; mp < 4; mp++)
        #pragma unroll
        for (int jj = 0; jj < 4; jj++) acc[mp][jj] = 0ull;

    // issue one 32-k chunk into buffer `buf`
    auto issue = [&](int ci, int buf) {
        const int kc = ci * 32;
        #pragma unroll
        for (int it = 0; it < 16; it++) {
            int idx = tid + it * 256;
            int m = idx >> 5, kk = idx & 31;
            int mg = m0 + m;
            const float* Wp = (mg < 256) ? Wq : ((mg < 512) ? Wk : Wv);
            cp4(&Ws[buf][kk][m], &Wp[(mg & 255) * 256 + kc + kk]);
        }
        #pragma unroll
        for (int it = 0; it < 2; it++) {
            int idx = tid + it * 256;
            int k = idx >> 4, j4 = idx & 15;
            cp16(&Xs[buf][k][j4 * 4], &x[(size_t)(b * NC + kc + k) * NP + n0 + j4 * 4]);
        }
        CP_COMMIT;
    };

    issue(0, 0);
    for (int ci = 0; ci < 8; ci++) {
        int nxt = (ci + 1 < 8) ? ci + 1 : 7;   // clamped redundant reload on last iter
        issue(nxt, (ci + 1) & 1);
        CP_WAIT(1);
        __syncthreads();
        const int buf = ci & 1;
        #pragma unroll 8
        for (int k = 0; k < 32; k++) {
            ulonglong2 w01 = *reinterpret_cast<const ulonglong2*>(&Ws[buf][k][ty * 8]);
            ulonglong2 w23 = *reinterpret_cast<const ulonglong2*>(&Ws[buf][k][ty * 8 + 4]);
            float4 xv = *reinterpret_cast<const float4*>(&Xs[buf][k][tx * 4]);
            ull wp[4] = { w01.x, w01.y, w23.x, w23.y };
            ull xd[4] = { pack2(xv.x, xv.x), pack2(xv.y, xv.y),
                          pack2(xv.z, xv.z), pack2(xv.w, xv.w) };
            #pragma unroll
            for (int mp = 0; mp < 4; mp++)
                #pragma unroll
                for (int jj = 0; jj < 4; jj++)
                    acc[mp][jj] = fma2(wp[mp], xd[jj], acc[mp][jj]);
        }
        __syncthreads();
    }
    CP_WAIT(0);

    const int sel = m0 >> 8;   // 0:q  1:k  2:v
    const int nbase = n0 + tx * 4;
    float mk[4]; int pr[4];
    #pragma unroll
    for (int jj = 0; jj < 4; jj++) {
        mk[jj] = mask[(size_t)b * NP + nbase + jj];
        pr[jj] = g_pr[(size_t)b * NP + nbase + jj];
    }

    #pragma unroll
    for (int mp = 0; mp < 4; mp++) {
        float2 u[4];
        #pragma unroll
        for (int jj = 0; jj < 4; jj++) u[jj] = unpack2(acc[mp][jj]);
        #pragma unroll
        for (int h = 0; h < 2; h++) {
            const int o = (m0 & 255) + ty * 8 + mp * 2 + h;
            float val[4];
            val[0] = h ? u[0].y : u[0].x;
            val[1] = h ? u[1].y : u[1].x;
            val[2] = h ? u[2].y : u[2].x;
            val[3] = h ? u[3].y : u[3].x;
            if (sel == 0) {
                const float bb = bq[o];
                float* dst = g_pq + (size_t)(b * NC + o) * NPQ;
                #pragma unroll
                for (int jj = 0; jj < 4; jj++)
                    if (mk[jj] > 0.5f) dst[pr[jj]] = val[jj] + bb;
            } else if (sel == 1) {
                const float bb = bk[o];
                float* dst = g_pk + (size_t)(b * NC + o) * NPQ;
                #pragma unroll
                for (int jj = 0; jj < 4; jj++)
                    if (mk[jj] < 0.5f) dst[pr[jj]] = val[jj] + bb;
            } else {
                const float bb = bv[o];
                #pragma unroll
                for (int jj = 0; jj < 4; jj++)
                    if (mk[jj] < 0.5f)
                        g_pv[((size_t)b * NPQ + pr[jj]) * NC + o] = val[jj] + bb;
            }
        }
    }
}

// ============================================================================
// Pad: write the shared bias column (bq/bk/bv) and zero padding to 64-mult.
// grid (8, 3), block 256.
// ============================================================================
__global__ __launch_bounds__(256, 1) void pad_kernel(
    const float* __restrict__ bq, const float* __restrict__ bk,
    const float* __restrict__ bv)
{
    const int b = blockIdx.x;
    const int sec = blockIdx.y;
    const int tid = threadIdx.x;
    const int nf = g_cnt[b * 2];
    const int nb = g_cnt[b * 2 + 1];

    if (sec == 0) {
        const int NQ = ((nf + 64) >> 6) << 6;   // pad(nf+1)
        const int npad = NQ - nf;
        for (int idx = tid; idx < npad * NC; idx += 256) {
            int c = idx / npad, p = nf + idx % npad;
            g_pq[(size_t)(b * NC + c) * NPQ + p] = (p == nf) ? bq[c] : 0.f;
        }
    } else if (sec == 1) {
        const int NK = ((nb + 64) >> 6) << 6;
        const int npad = NK - nb;
        for (int idx = tid; idx < npad * NC; idx += 256) {
            int c = idx / npad, p = nb + idx % npad;
            g_pk[(size_t)(b * NC + c) * NPQ + p] = (p == nb) ? bk[c] : 0.f;
        }
    } else {
        const int NK = ((nb + 64) >> 6) << 6;
        for (int p = nb; p < NK; p++)
            g_pv[((size_t)b * NPQ + p) * NC + tid] = (p == nb) ? bv[tid] : 0.f;
    }
}

// ============================================================================
// Kernel B: flash attention on compacted columns, weighted shared key.
// cp.async schedule: V_t load overlaps S_t; K_{t+1} load overlaps PV_t.
// Single buffers, 3 barriers/tile. grid (65 q-tiles, 8 b), block 256.
// ============================================================================
__global__ __launch_bounds__(256, 1) void attn_kernel()
{
    extern __shared__ float smf[];
    float* Qs  = smf;             // 16384
    float* Ks  = smf + 16384;     // 16384
    float* Vst = smf + 32768;     // 16384 : [j][c]
    float* Ps  = smf + 49152;     // 4096  : [i][j]

    const int tid = threadIdx.x;
    const int tx = tid & 15;
    const int ty = tid >> 4;
    const int b  = blockIdx.y;
    const int i0 = blockIdx.x * 64;

    const int nf = g_cnt[b * 2];
    const int nb = g_cnt[b * 2 + 1];
    if (i0 >= nf + 1) return;
    const int nkt = (nb + 1 + 63) >> 6;
    const float wF = (float)nf;

    // prologue: Q + K_0 (one group)
    #pragma unroll
    for (int it = 0; it < 16; it++) {
        int idx = tid + it * 256;
        int c = idx >> 4, i4 = idx & 15;
        cp16(&Qs[c * 64 + i4 * 4], &g_pq[(size_t)(b * NC + c) * NPQ + i0 + i4 * 4]);
    }
    #pragma unroll
    for (int it = 0; it < 16; it++) {
        int idx = tid + it * 256;
        int c = idx >> 4, j4 = idx & 15;
        cp16(&Ks[c * 64 + j4 * 4], &g_pk[(size_t)(b * NC + c) * NPQ + j4 * 4]);
    }
    CP_COMMIT;

    float m_i[4], l_i[4];
    #pragma unroll
    for (int ii = 0; ii < 4; ii++) { m_i[ii] = -1e30f; l_i[ii] = 0.f; }
    ulonglong2 oa[4][4];
    #pragma unroll
    for (int cc = 0; cc < 4; cc++)
        #pragma unroll
        for (int ii = 0; ii < 4; ii++) { oa[cc][ii].x = 0ull; oa[cc][ii].y = 0ull; }

    for (int jt = 0; jt < nkt; jt++) {
        const int j0 = jt * 64;

        // issue V_t (overlaps S_t); V buffer free (post-PV barrier of prev iter)
        #pragma unroll
        for (int it = 0; it < 16; it++) {
            int idx = tid + it * 256;
            int j = idx >> 6, c4 = idx & 63;
            cp16(&Vst[j * 256 + c4 * 4], &g_pv[((size_t)b * NPQ + j0 + j) * NC + c4 * 4]);
        }
        CP_COMMIT;
        CP_WAIT(1);          // K_t (and Q) complete, V_t may be in flight
        __syncthreads();     // barrier 1: K_t visible block-wide

        // ---- S = Q^T K ----
        ull s2[2][4];
        #pragma unroll
        for (int ip = 0; ip < 2; ip++)
            #pragma unroll
            for (int jj = 0; jj < 4; jj++) s2[ip][jj] = 0ull;

        #pragma unroll 4
        for (int c = 0; c < NC; c++) {
            ulonglong2 q2 = *reinterpret_cast<const ulonglong2*>(&Qs[c * 64 + ty * 4]);
            float4 k4 = *reinterpret_cast<const float4*>(&Ks[c * 64 + tx * 4]);
            ull kd[4] = { pack2(k4.x, k4.x), pack2(k4.y, k4.y),
                          pack2(k4.z, k4.z), pack2(k4.w, k4.w) };
            #pragma unroll
            for (int jj = 0; jj < 4; jj++) {
                s2[0][jj] = fma2(q2.x, kd[jj], s2[0][jj]);
                s2[1][jj] = fma2(q2.y, kd[jj], s2[1][jj]);
            }
        }

        float sv[4][4];
        #pragma unroll
        for (int ip = 0; ip < 2; ip++)
            #pragma unroll
            for (int jj = 0; jj < 4; jj++) {
                float2 u = unpack2(s2[ip][jj]);
                sv[ip * 2 + 0][jj] = u.x;
                sv[ip * 2 + 1][jj] = u.y;
            }

        const int jbase = j0 + tx * 4;
        float w[4];
        #pragma unroll
        for (int jj = 0; jj < 4; jj++) {
            int jg = jbase + jj;
            w[jj] = (jg == nb) ? wF : 1.f;
            if (jg > nb) {
                #pragma unroll
                for (int ii = 0; ii < 4; ii++) sv[ii][jj] = -1e30f;
            }
        }

        // ---- online softmax ----
        float al[4];
        #pragma unroll
        for (int ii = 0; ii < 4; ii++) {
            float rm = fmaxf(fmaxf(sv[ii][0], sv[ii][1]), fmaxf(sv[ii][2], sv[ii][3]));
            #pragma unroll
            for (int off = 8; off > 0; off >>= 1)
                rm = fmaxf(rm, __shfl_xor_sync(0xffffffffu, rm, off));
            float mn = fmaxf(m_i[ii], rm);
            al[ii] = __expf(m_i[ii] - mn);
            float rs = 0.f;
            #pragma unroll
            for (int jj = 0; jj < 4; jj++) {
                float p = __expf(sv[ii][jj] - mn) * w[jj];
                sv[ii][jj] = p;
                rs += p;
            }
            #pragma unroll
            for (int off = 8; off > 0; off >>= 1)
                rs += __shfl_xor_sync(0xffffffffu, rs, off);
            l_i[ii] = l_i[ii] * al[ii] + rs;
            m_i[ii] = mn;
            *reinterpret_cast<float4*>(&Ps[(ty * 4 + ii) * 64 + tx * 4]) =
                make_float4(sv[ii][0], sv[ii][1], sv[ii][2], sv[ii][3]);
            ull ad = pack2(al[ii], al[ii]);
            #pragma unroll
            for (int cc = 0; cc < 4; cc++) {
                oa[cc][ii].x = mul2(oa[cc][ii].x, ad);
                oa[cc][ii].y = mul2(oa[cc][ii].y, ad);
            }
        }

        CP_WAIT(0);          // V_t complete (own parts)
        __syncthreads();     // barrier 2: V_t + Ps visible; all warps done with K_t

        // prefetch K_{t+1} (overlaps PV_t); clamp to avoid OOB on last iter
        {
            const int jn = ((jt + 1 < nkt) ? jt + 1 : nkt - 1) * 64;
            #pragma unroll
            for (int it = 0; it < 16; it++) {
                int idx = tid + it * 256;
                int c = idx >> 4, j4 = idx & 15;
                cp16(&Ks[c * 64 + j4 * 4], &g_pk[(size_t)(b * NC + c) * NPQ + jn + j4 * 4]);
            }
            CP_COMMIT;
        }

        // ---- O += V @ P^T ----
        for (int j4 = 0; j4 < 16; j4++) {
            float4 pr[4];
            #pragma unroll
            for (int ii = 0; ii < 4; ii++)
                pr[ii] = *reinterpret_cast<const float4*>(&Ps[(ty * 4 + ii) * 64 + j4 * 4]);
            #pragma unroll
            for (int dj = 0; dj < 4; dj++) {
                int j = j4 * 4 + dj;
                ulonglong2 vv[4];
                #pragma unroll
                for (int cc = 0; cc < 4; cc++)
                    vv[cc] = *reinterpret_cast<const ulonglong2*>(&Vst[j * 256 + cc * 64 + tx * 4]);
                #pragma unroll
                for (int ii = 0; ii < 4; ii++) {
                    float p = (dj == 0) ? pr[ii].x : (dj == 1) ? pr[ii].y
                            : (dj == 2) ? pr[ii].z : pr[ii].w;
                    ull pd = pack2(p, p);
                    #pragma unroll
                    for (int cc = 0; cc < 4; cc++) {
                        oa[cc][ii].x = fma2(vv[cc].x, pd, oa[cc][ii].x);
                        oa[cc][ii].y = fma2(vv[cc].y, pd, oa[cc][ii].y);
                    }
                }
            }
        }
        __syncthreads();     // barrier 3: all done reading V_t (safe for next V issue)
    }
    CP_WAIT(0);

    float inv[4];
    #pragma unroll
    for (int ii = 0; ii < 4; ii++) inv[ii] = 1.f / l_i[ii];

    #pragma unroll
    for (int cc = 0; cc < 4; cc++) {
        float of[4][4];
        #pragma unroll
        for (int ii = 0; ii < 4; ii++) {
            float2 u0 = unpack2(oa[cc][ii].x);
            float2 u1 = unpack2(oa[cc][ii].y);
            of[ii][0] = u0.x * inv[ii];
            of[ii][1] = u0.y * inv[ii];
            of[ii][2] = u1.x * inv[ii];
            of[ii][3] = u1.y * inv[ii];
        }
        #pragma unroll
        for (int d = 0; d < 4; d++) {
            int c = cc * 64 + tx * 4 + d;
            *reinterpret_cast<float4*>(&g_go[(size_t)(b * NC + c) * NPQ + i0 + ty * 4]) =
                make_float4(of[0][d], of[1][d], of[2][d], of[3][d]);
        }
    }
}

// ============================================================================
// Kernel C: output projection on packed columns: g_p = Wo@go + bo
// grid (65 n-tiles, 2 m-tiles, 8 b), early exit.
// ============================================================================
__global__ __launch_bounds__(256, 1) void proj_kernel(
    const float* __restrict__ Wo, const float* __restrict__ bo)
{
    __shared__ float Ws[32][132];
    __shared__ float Xs[32][64];

    const int tid = threadIdx.x;
    const int tx = tid & 15;
    const int ty = tid >> 4;
    const int n0 = blockIdx.x * 64;
    const int m0 = blockIdx.y * 128;
    const int b  = blockIdx.z;

    const int nfq = g_cnt[b * 2] + 1;
    if (n0 >= nfq) return;

    ull acc[4][4];
    #pragma unroll
    for (int mp = 0; mp < 4; mp++)
        #pragma unroll
        for (int jj = 0; jj < 4; jj++) acc[mp][jj] = 0ull;

    for (int kc = 0; kc < NC; kc += 32) {
        #pragma unroll
        for (int it = 0; it < 16; it++) {
            int idx = tid + it * 256;
            int m = idx >> 5, kk = idx & 31;
            Ws[kk][m] = Wo[(m0 + m) * 256 + kc + kk];
        }
        #pragma unroll
        for (int it = 0; it < 2; it++) {
            int idx = tid + it * 256;
            int k = idx >> 4, j4 = idx & 15;
            *reinterpret_cast<float4*>(&Xs[k][j4 * 4]) =
                *reinterpret_cast<const float4*>(&g_go[(size_t)(b * NC + kc + k) * NPQ + n0 + j4 * 4]);
        }
        __syncthreads();
        #pragma unroll 8
        for (int k = 0; k < 32; k++) {
            ulonglong2 w01 = *reinterpret_cast<const ulonglong2*>(&Ws[k][ty * 8]);
            ulonglong2 w23 = *reinterpret_cast<const ulonglong2*>(&Ws[k][ty * 8 + 4]);
            float4 xv = *reinterpret_cast<const float4*>(&Xs[k][tx * 4]);
            ull wp[4] = { w01.x, w01.y, w23.x, w23.y };
            ull xd[4] = { pack2(xv.x, xv.x), pack2(xv.y, xv.y),
                          pack2(xv.z, xv.z), pack2(xv.w, xv.w) };
            #pragma unroll
            for (int mp = 0; mp < 4; mp++)
                #pragma unroll
                for (int jj = 0; jj < 4; jj++)
                    acc[mp][jj] = fma2(wp[mp], xd[jj], acc[mp][jj]);
        }
        __syncthreads();
    }

    #pragma unroll
    for (int mp = 0; mp < 4; mp++) {
        float2 u[4];
        #pragma unroll
        for (int jj = 0; jj < 4; jj++) u[jj] = unpack2(acc[mp][jj]);
        #pragma unroll
        for (int h = 0; h < 2; h++) {
            int o = m0 + ty * 8 + mp * 2 + h;
            float bb = bo[o];
            float4 r;
            r.x = (h ? u[0].y : u[0].x) + bb;
            r.y = (h ? u[1].y : u[1].x) + bb;
            r.z = (h ? u[2].y : u[2].x) + bb;
            r.w = (h ? u[3].y : u[3].x) + bb;
            *reinterpret_cast<float4*>(&g_p[(size_t)(b * NC + o) * NPQ + n0 + tx * 4]) = r;
        }
    }
}

// ============================================================================
// Scatter: out[b][c][n] = g_p[b][c][cidx[n]] + gamma * x[b][c][n]
// ============================================================================
__global__ __launch_bounds__(256, 1) void scatter_kernel(
    const float* __restrict__ x, const float* __restrict__ gamma,
    float* __restrict__ out)
{
    const int b = blockIdx.y;
    const int n = blockIdx.x * 256 + threadIdx.x;
    const int ci = g_cidx[(size_t)b * NP + n];
    const float g0 = gamma[0];

    const float* px = x + (size_t)b * NC * NP + n;
    const float* pp = g_p + (size_t)b * NC * NPQ + ci;
    float* po = out + (size_t)b * NC * NP + n;

    #pragma unroll 4
    for (int c = 0; c < NC; c++) {
        po[(size_t)c * NP] = pp[(size_t)c * NPQ] + g0 * px[(size_t)c * NP];
    }
}

extern "C" void kernel_launch(void* const* d_in, const int* in_sizes, int n_in,
                              void* d_out, int out_size)
{
    const float* x     = (const float*)d_in[0];
    const float* mask  = (const float*)d_in[1];
    const float* Wq    = (const float*)d_in[2];
    const float* bq    = (const float*)d_in[3];
    const float* Wk    = (const float*)d_in[4];
    const float* bk    = (const float*)d_in[5];
    const float* Wv    = (const float*)d_in[6];
    const float* bv    = (const float*)d_in[7];
    const float* Wo    = (const float*)d_in[8];
    const float* bo    = (const float*)d_in[9];
    const float* gamma = (const float*)d_in[10];
    float* out = (float*)d_out;

    compact_kernel<<<NB, 256>>>(mask);
    qkv_kernel<<<dim3(64, 6, NB), 256>>>(x, mask, Wq, bq, Wk, bk, Wv, bv);
    pad_kernel<<<dim3(NB, 3), 256>>>(bq, bk, bv);

    const size_t smemB = (size_t)(16384 * 3 + 4096) * sizeof(float);  // 212992 B
    cudaFuncSetAttribute(attn_kernel, cudaFuncAttributeMaxDynamicSharedMemorySize, (int)smemB);
    attn_kernel<<<dim3(65, NB), 256, smemB>>>();

    proj_kernel<<<dim3(65, 2, NB), 256>>>(Wo, bo);
    scatter_kernel<<<dim3(16, NB), 256>>>(x, gamma, out);
}